// round 15
// baseline (speedup 1.0000x reference)
#include <cuda_runtime.h>
#include <cuda_fp16.h>
#include <cstdint>

#define NN 116
#define HH 128
#define NTHREADS 512
#define STR 136            // row stride in HALFS; 272B rows -> ldmatrix conflict-free

static constexpr size_t SMEM_BYTES = (size_t)(3 * 128 * STR) * sizeof(__half);  // 104448

__device__ __forceinline__ uint32_t smem_u32(const void* p) {
    uint32_t a;
    asm("{ .reg .u64 t; cvta.to.shared.u64 t, %1; cvt.u32.u64 %0, t; }" : "=r"(a) : "l"(p));
    return a;
}

#define LDSM4(r0, r1, r2, r3, addr)                                           \
    asm volatile("ldmatrix.sync.aligned.m8n8.x4.shared.b16 {%0,%1,%2,%3}, [%4];" \
                 : "=r"(r0), "=r"(r1), "=r"(r2), "=r"(r3) : "r"(addr))

#define MMA_F16(d, a, b)                                                      \
    asm volatile(                                                             \
        "mma.sync.aligned.m16n8k16.row.col.f32.f16.f16.f32 "                  \
        "{%0,%1,%2,%3}, {%4,%5,%6,%7}, {%8,%9}, {%0,%1,%2,%3};"               \
        : "+f"(d[0]), "+f"(d[1]), "+f"(d[2]), "+f"(d[3])                      \
        : "r"(a[0]), "r"(a[1]), "r"(a[2]), "r"(a[3]), "r"(b[0]), "r"(b[1]))

// 128-thread named group barrier
#define GBAR(id) asm volatile("bar.sync %0, %1;" :: "r"(id), "r"(128) : "memory")

// 128x128x128 fp16 GEMM; 16 warps in 4x4 grid; warp tile 32(m) x 32(n).
// A: [m][k], B: [n][k]; per k-step (K=16) 2+2 LDSM.x4 + 8 MMA.  (R10-proven)
__device__ __forceinline__ void gemm_h(const __half* __restrict__ Aop,
                                       const __half* __restrict__ Bop,
                                       float acc[2][4][4],
                                       int wm, int wn, int lane)
{
    #pragma unroll
    for (int mi = 0; mi < 2; mi++)
        #pragma unroll
        for (int ni = 0; ni < 4; ni++)
            #pragma unroll
            for (int q = 0; q < 4; q++) acc[mi][ni][q] = 0.f;

    const int t = lane >> 3, ri = lane & 7;

    uint32_t aAm[2];
    #pragma unroll
    for (int mi = 0; mi < 2; mi++)
        aAm[mi] = smem_u32(Aop + (wm * 32 + mi * 16 + (t & 1) * 8 + ri) * STR) + (t >> 1) * 16;
    uint32_t aBp[2];
    #pragma unroll
    for (int pi = 0; pi < 2; pi++)
        aBp[pi] = smem_u32(Bop + (wn * 32 + pi * 16 + (t >> 1) * 8 + ri) * STR) + (t & 1) * 16;

    #pragma unroll
    for (int ks = 0; ks < 8; ks++) {
        const uint32_t kb = ks * 32;
        uint32_t fa[2][4], fb[4][2];
        #pragma unroll
        for (int mi = 0; mi < 2; mi++)
            LDSM4(fa[mi][0], fa[mi][1], fa[mi][2], fa[mi][3], aAm[mi] + kb);
        #pragma unroll
        for (int pi = 0; pi < 2; pi++)
            LDSM4(fb[2 * pi][0], fb[2 * pi][1], fb[2 * pi + 1][0], fb[2 * pi + 1][1],
                  aBp[pi] + kb);
        #pragma unroll
        for (int mi = 0; mi < 2; mi++)
            #pragma unroll
            for (int ni = 0; ni < 4; ni++)
                MMA_F16(acc[mi][ni], fa[mi], fb[ni]);
    }
}

__global__ __launch_bounds__(NTHREADS, 2)
void gcn_mma(const float* __restrict__ ga, const float* __restrict__ gf,
             const float* __restrict__ gW1, const float* __restrict__ gb1,
             const float* __restrict__ gW2, const float* __restrict__ gb2,
             float* __restrict__ gout)
{
    extern __shared__ __half sh[];
    __half* sA = sh;                  // A_norm    [m][k]  [128][STR]
    __half* sX = sh + 128 * STR;      // f -> h    [m][k]  [128][STR]
    __half* sB = sh + 2 * 128 * STR;  // W1/g/W2/t [n][k]  [128][STR]
    __shared__ float sd[128], sb1[128], sb2[128];

    const int tid = threadIdx.x;
    const int wid = tid >> 5, lane = tid & 31;
    const int wm = wid & 3, wn = wid >> 2;   // 4x4 warp grid -> 32x32 tiles
    const int bn = 1 + wn;   // n-group barrier id (warps sharing sB band wn)
    const int bm = 5 + wm;   // m-group barrier id (warps sharing sA/sX band wm)
    const int b = blockIdx.x;
    const float* ab = ga + (size_t)b * NN * NN;
    const float* fg = gf + (size_t)b * NN * NN;
    float*       ob = gout + (size_t)b * NN * HH;

    const int rA = wm * 32 + wn * 8;   // this warp's owned sA/sX rows
    const int rB = wn * 32 + wm * 8;   // this warp's owned sB rows

    // ---- zero-fill OWNED rows (full rows, uint4: 17 chunks x 8 rows/buffer) ----
    {
        uint4 z = make_uint4(0u, 0u, 0u, 0u);
        for (int e = lane; e < 8 * 17; e += 32) {
            int rr = e / 17, c = e - rr * 17;
            reinterpret_cast<uint4*>(sA + (rA + rr) * STR)[c] = z;
            reinterpret_cast<uint4*>(sX + (rA + rr) * STR)[c] = z;
            reinterpret_cast<uint4*>(sB + (rB + rr) * STR)[c] = z;
        }
    }
    if (tid < 128) { sb1[tid] = __ldg(gb1 + tid); sb2[tid] = __ldg(gb2 + tid); }

    // ---- rowsums of |a| from gmem -> sd (consumed after the global bar) ----
    for (int row = wid; row < NN; row += 16) {
        const float* rp = ab + row * NN;
        float s = 0.f;
        #pragma unroll
        for (int jj = 0; jj < 4; jj++) {
            int j = lane + jj * 32;
            if (j < NN) s += fabsf(__ldg(rp + j));
        }
        #pragma unroll
        for (int o = 16; o; o >>= 1) s += __shfl_xor_sync(0xffffffffu, s, o);
        if (!lane) sd[row] = rsqrtf(s + 1.0f);
    }

    // ---- f -> sX (owned rows, coalesced) ----
    for (int rr = 0; rr < 8; rr++) {
        int i = rA + rr;
        if (i >= NN) break;
        const float* fp = fg + i * NN;
        for (int j = lane; j < NN; j += 32)
            sX[i * STR + j] = __float2half_rn(__ldg(fp + j));
    }
    // ---- W1 -> sB band wn (group-cooperative, coalesced gmem) ----
    for (int e = wm * 32 + lane; e < 32 * NN; e += 128) {
        int k = e >> 5, n = wn * 32 + (e & 31);
        sB[n * STR + k] = __float2half_rn(__ldg(gW1 + k * HH + n));
    }
    GBAR(bn);
    GBAR(bm);

    const int r = lane >> 2, c2 = (lane & 3) * 2;
    float acc[2][4][4];

    // ===== G1: g = f @ W1 =====
    gemm_h(sX, sB, acc, wm, wn, lane);
    __syncthreads();   // the ONE global bar: sd/sb ready; all G1 reads complete

    // epi1: g -> sB band wn (transposed scalar stores)
    #pragma unroll
    for (int mi = 0; mi < 2; mi++)
        #pragma unroll
        for (int ni = 0; ni < 4; ni++) {
            int row = wm * 32 + mi * 16 + r, col = wn * 32 + ni * 8 + c2;
            sB[col * STR + row]           = __float2half_rn(acc[mi][ni][0]);
            sB[(col + 1) * STR + row]     = __float2half_rn(acc[mi][ni][1]);
            sB[col * STR + row + 8]       = __float2half_rn(acc[mi][ni][2]);
            sB[(col + 1) * STR + row + 8] = __float2half_rn(acc[mi][ni][3]);
        }
    // A_norm -> sA owned rows (f in sX dead only as... sA untouched so far; needs sd)
    for (int rr = 0; rr < 8; rr++) {
        int i = rA + rr;
        if (i >= NN) break;
        float di = sd[i];
        const float* ap = ab + i * NN;
        for (int j = lane; j < NN; j += 32) {
            float v = fabsf(__ldg(ap + j)) + (i == j ? 1.0f : 0.0f);
            sA[i * STR + j] = __float2half_rn(di * sd[j] * v);
        }
    }
    GBAR(bn);   // g visible within n-group
    GBAR(bm);   // A_norm visible within m-group

    // ===== G2: h = relu(A_norm @ g + b1) =====
    gemm_h(sA, sB, acc, wm, wn, lane);
    // h -> sX band wm (safe: last sX readers were G1, covered by global bar)
    #pragma unroll
    for (int mi = 0; mi < 2; mi++)
        #pragma unroll
        for (int ni = 0; ni < 4; ni++) {
            int row = wm * 32 + mi * 16 + r, col = wn * 32 + ni * 8 + c2;
            *reinterpret_cast<__half2*>(sX + row * STR + col) =
                __floats2half2_rn(fmaxf(acc[mi][ni][0] + sb1[col], 0.f),
                                  fmaxf(acc[mi][ni][1] + sb1[col + 1], 0.f));
            *reinterpret_cast<__half2*>(sX + (row + 8) * STR + col) =
                __floats2half2_rn(fmaxf(acc[mi][ni][2] + sb1[col], 0.f),
                                  fmaxf(acc[mi][ni][3] + sb1[col + 1], 0.f));
        }
    GBAR(bn);   // n-group done reading g before W2 overwrites band
    // W2 -> sB band wn (group-cooperative)
    for (int e = wm * 32 + lane; e < 32 * HH; e += 128) {
        int k = e >> 5, n = wn * 32 + (e & 31);
        sB[n * STR + k] = __float2half_rn(__ldg(gW2 + k * HH + n));
    }
    GBAR(bn);   // W2 visible
    GBAR(bm);   // h visible

    // ===== G3: t = h @ W2 =====
    gemm_h(sX, sB, acc, wm, wn, lane);
    GBAR(bn);   // n-group done reading W2
    // epi3: t -> sB band wn
    #pragma unroll
    for (int mi = 0; mi < 2; mi++)
        #pragma unroll
        for (int ni = 0; ni < 4; ni++) {
            int row = wm * 32 + mi * 16 + r, col = wn * 32 + ni * 8 + c2;
            sB[col * STR + row]           = __float2half_rn(acc[mi][ni][0]);
            sB[(col + 1) * STR + row]     = __float2half_rn(acc[mi][ni][1]);
            sB[col * STR + row + 8]       = __float2half_rn(acc[mi][ni][2]);
            sB[(col + 1) * STR + row + 8] = __float2half_rn(acc[mi][ni][3]);
        }
    GBAR(bn);   // t visible

    // ===== G4: out = relu(A_norm @ t + b2) =====
    gemm_h(sA, sB, acc, wm, wn, lane);
    #pragma unroll
    for (int mi = 0; mi < 2; mi++)
        #pragma unroll
        for (int ni = 0; ni < 4; ni++) {
            int row = wm * 32 + mi * 16 + r, col = wn * 32 + ni * 8 + c2;
            if (row < NN) {
                float2 v0 = make_float2(fmaxf(acc[mi][ni][0] + sb2[col], 0.f),
                                        fmaxf(acc[mi][ni][1] + sb2[col + 1], 0.f));
                *reinterpret_cast<float2*>(ob + (size_t)row * HH + col) = v0;
            }
            if (row + 8 < NN) {
                float2 v1 = make_float2(fmaxf(acc[mi][ni][2] + sb2[col], 0.f),
                                        fmaxf(acc[mi][ni][3] + sb2[col + 1], 0.f));
                *reinterpret_cast<float2*>(ob + (size_t)(row + 8) * HH + col) = v1;
            }
        }
}

extern "C" void kernel_launch(void* const* d_in, const int* in_sizes, int n_in,
                              void* d_out, int out_size)
{
    const float* a  = (const float*)d_in[0];
    const float* f  = (const float*)d_in[1];
    const float* W1 = (const float*)d_in[2];
    const float* b1 = (const float*)d_in[3];
    const float* W2 = (const float*)d_in[4];
    const float* b2 = (const float*)d_in[5];
    float* out = (float*)d_out;

    int batch = in_sizes[0] / (NN * NN);

    cudaFuncSetAttribute(gcn_mma, cudaFuncAttributeMaxDynamicSharedMemorySize, (int)SMEM_BYTES);
    gcn_mma<<<batch, NTHREADS, SMEM_BYTES>>>(a, f, W1, b1, W2, b2, out);
}

// round 16
// speedup vs baseline: 1.5701x; 1.5701x over previous
#include <cuda_runtime.h>
#include <cuda_fp16.h>
#include <cstdint>

#define NN 116
#define HH 128
#define NTHREADS 512
#define STR 136            // row stride in HALFS; 272B rows -> ldmatrix conflict-free

static constexpr size_t SMEM_BYTES = (size_t)(3 * 128 * STR) * sizeof(__half);  // 104448

__device__ __forceinline__ uint32_t smem_u32(const void* p) {
    uint32_t a;
    asm("{ .reg .u64 t; cvta.to.shared.u64 t, %1; cvt.u32.u64 %0, t; }" : "=r"(a) : "l"(p));
    return a;
}

#define LDSM4(r0, r1, r2, r3, addr)                                           \
    asm volatile("ldmatrix.sync.aligned.m8n8.x4.shared.b16 {%0,%1,%2,%3}, [%4];" \
                 : "=r"(r0), "=r"(r1), "=r"(r2), "=r"(r3) : "r"(addr))

#define MMA_F16(d, a, b)                                                      \
    asm volatile(                                                             \
        "mma.sync.aligned.m16n8k16.row.col.f32.f16.f16.f32 "                  \
        "{%0,%1,%2,%3}, {%4,%5,%6,%7}, {%8,%9}, {%0,%1,%2,%3};"               \
        : "+f"(d[0]), "+f"(d[1]), "+f"(d[2]), "+f"(d[3])                      \
        : "r"(a[0]), "r"(a[1]), "r"(a[2]), "r"(a[3]), "r"(b[0]), "r"(b[1]))

// 128x128x128 fp16 GEMM; 16 warps in 4x4 grid; warp tile 32(m) x 32(n).
// Per k-step: 2 LDSM.x4 (A) + 2 LDSM.x4 (B) + 8 MMA.
__device__ __forceinline__ void gemm_h(const __half* __restrict__ Aop,
                                       const __half* __restrict__ Bop,
                                       float acc[2][4][4],
                                       int wm, int wn, int lane)
{
    #pragma unroll
    for (int mi = 0; mi < 2; mi++)
        #pragma unroll
        for (int ni = 0; ni < 4; ni++)
            #pragma unroll
            for (int q = 0; q < 4; q++) acc[mi][ni][q] = 0.f;

    const int t = lane >> 3, ri = lane & 7;

    // A tile mi: rows wm*32 + mi*16 + (t&1)*8 + ri, k-half (t>>1)
    uint32_t aAm[2];
    #pragma unroll
    for (int mi = 0; mi < 2; mi++)
        aAm[mi] = smem_u32(Aop + (wm * 32 + mi * 16 + (t & 1) * 8 + ri) * STR) + (t >> 1) * 16;
    // B pair pi: n-rows wn*32 + pi*16 + (t>>1)*8 + ri, k-half (t&1)
    uint32_t aBp[2];
    #pragma unroll
    for (int pi = 0; pi < 2; pi++)
        aBp[pi] = smem_u32(Bop + (wn * 32 + pi * 16 + (t >> 1) * 8 + ri) * STR) + (t & 1) * 16;

    #pragma unroll
    for (int ks = 0; ks < 8; ks++) {
        const uint32_t kb = ks * 32;     // 16 halfs = 32 bytes
        uint32_t fa[2][4], fb[4][2];
        #pragma unroll
        for (int mi = 0; mi < 2; mi++)
            LDSM4(fa[mi][0], fa[mi][1], fa[mi][2], fa[mi][3], aAm[mi] + kb);
        #pragma unroll
        for (int pi = 0; pi < 2; pi++)
            LDSM4(fb[2 * pi][0], fb[2 * pi][1], fb[2 * pi + 1][0], fb[2 * pi + 1][1],
                  aBp[pi] + kb);
        #pragma unroll
        for (int mi = 0; mi < 2; mi++)
            #pragma unroll
            for (int ni = 0; ni < 4; ni++)
                MMA_F16(acc[mi][ni], fa[mi], fb[ni]);
    }
}

__global__ __launch_bounds__(NTHREADS, 2)
void gcn_mma(const float* __restrict__ ga, const float* __restrict__ gf,
             const float* __restrict__ gW1, const float* __restrict__ gb1,
             const float* __restrict__ gW2, const float* __restrict__ gb2,
             float* __restrict__ gout)
{
    extern __shared__ __half sh[];
    __half* sA = sh;                  // A_norm    [m][k]  [128][STR]
    __half* sX = sh + 128 * STR;      // f -> h    [m][k]  [128][STR]
    __half* sB = sh + 2 * 128 * STR;  // W1/g/W2/t [n][k]  [128][STR]
    __shared__ float sd[128], sb1[128], sb2[128];

    const int tid = threadIdx.x;
    const int wid = tid >> 5, lane = tid & 31;
    const int wm = wid & 3, wn = wid >> 2;   // 4x4 warp grid -> 32x32 tiles
    const int b = blockIdx.x;
    const float* ab = ga + (size_t)b * NN * NN;
    const float* fg = gf + (size_t)b * NN * NN;
    float*       ob = gout + (size_t)b * NN * HH;

    // ---- zero all operand buffers ----
    for (int i = tid; i < 6528; i += NTHREADS)
        reinterpret_cast<uint4*>(sh)[i] = make_uint4(0u, 0u, 0u, 0u);
    if (tid < 128) { sb1[tid] = __ldg(gb1 + tid); sb2[tid] = __ldg(gb2 + tid); }

    // ---- pass 1: rowsums of |a| straight from gmem -> d ----
    for (int row = wid; row < NN; row += 16) {
        const float* rp = ab + row * NN;
        float s = 0.f;
        #pragma unroll
        for (int jj = 0; jj < 4; jj++) {
            int j = lane + jj * 32;
            if (j < NN) s += fabsf(__ldg(rp + j));
        }
        #pragma unroll
        for (int o = 16; o; o >>= 1) s += __shfl_xor_sync(0xffffffffu, s, o);
        if (!lane) sd[row] = rsqrtf(s + 1.0f);
    }
    __syncthreads();

    // ---- pass 2: A_norm(half), f(half) [m][k]; W1(half) [n][k] ----
    for (int idx = tid; idx < NN * NN; idx += NTHREADS) {
        int i = idx / NN, j = idx - i * NN;
        float v = fabsf(__ldg(ab + idx)) + (i == j ? 1.0f : 0.0f);
        sA[i * STR + j] = __float2half_rn(sd[i] * sd[j] * v);
        sX[i * STR + j] = __float2half_rn(__ldg(fg + idx));
    }
    for (int idx = tid; idx < NN * HH; idx += NTHREADS) {
        int k = idx >> 7, n = idx & 127;
        sB[n * STR + k] = __float2half_rn(__ldg(gW1 + idx));
    }
    __syncthreads();

    const int r = lane >> 2, c2 = (lane & 3) * 2;
    float acc[2][4][4];

    // ===== G1: g = f @ W1 =====
    gemm_h(sX, sB, acc, wm, wn, lane);
    __syncthreads();                          // all warps done reading W1
    #pragma unroll
    for (int mi = 0; mi < 2; mi++)
        #pragma unroll
        for (int ni = 0; ni < 4; ni++) {
            int row = wm * 32 + mi * 16 + r, col = wn * 32 + ni * 8 + c2;
            sB[col * STR + row]           = __float2half_rn(acc[mi][ni][0]);
            sB[(col + 1) * STR + row]     = __float2half_rn(acc[mi][ni][1]);
            sB[col * STR + row + 8]       = __float2half_rn(acc[mi][ni][2]);
            sB[(col + 1) * STR + row + 8] = __float2half_rn(acc[mi][ni][3]);
        }
    __syncthreads();

    // ===== G2: h = relu(A_norm @ g + b1) =====
    gemm_h(sA, sB, acc, wm, wn, lane);
    __syncthreads();                          // all warps done reading g
    #pragma unroll
    for (int mi = 0; mi < 2; mi++)
        #pragma unroll
        for (int ni = 0; ni < 4; ni++) {
            int row = wm * 32 + mi * 16 + r, col = wn * 32 + ni * 8 + c2;
            *reinterpret_cast<__half2*>(sX + row * STR + col) =
                __floats2half2_rn(fmaxf(acc[mi][ni][0] + sb1[col], 0.f),
                                  fmaxf(acc[mi][ni][1] + sb1[col + 1], 0.f));
            *reinterpret_cast<__half2*>(sX + (row + 8) * STR + col) =
                __floats2half2_rn(fmaxf(acc[mi][ni][2] + sb1[col], 0.f),
                                  fmaxf(acc[mi][ni][3] + sb1[col + 1], 0.f));
        }
    for (int idx = tid; idx < HH * HH; idx += NTHREADS) {
        int k = idx >> 7, n = idx & 127;
        sB[n * STR + k] = __float2half_rn(__ldg(gW2 + idx));
    }
    __syncthreads();

    // ===== G3: t = h @ W2 =====
    gemm_h(sX, sB, acc, wm, wn, lane);
    __syncthreads();                          // all warps done reading W2
    #pragma unroll
    for (int mi = 0; mi < 2; mi++)
        #pragma unroll
        for (int ni = 0; ni < 4; ni++) {
            int row = wm * 32 + mi * 16 + r, col = wn * 32 + ni * 8 + c2;
            sB[col * STR + row]           = __float2half_rn(acc[mi][ni][0]);
            sB[(col + 1) * STR + row]     = __float2half_rn(acc[mi][ni][1]);
            sB[col * STR + row + 8]       = __float2half_rn(acc[mi][ni][2]);
            sB[(col + 1) * STR + row + 8] = __float2half_rn(acc[mi][ni][3]);
        }
    __syncthreads();

    // ===== G4: out = relu(A_norm @ t + b2) =====
    gemm_h(sA, sB, acc, wm, wn, lane);
    #pragma unroll
    for (int mi = 0; mi < 2; mi++)
        #pragma unroll
        for (int ni = 0; ni < 4; ni++) {
            int row = wm * 32 + mi * 16 + r, col = wn * 32 + ni * 8 + c2;
            if (row < NN) {
                float2 v0 = make_float2(fmaxf(acc[mi][ni][0] + sb2[col], 0.f),
                                        fmaxf(acc[mi][ni][1] + sb2[col + 1], 0.f));
                *reinterpret_cast<float2*>(ob + (size_t)row * HH + col) = v0;
            }
            if (row + 8 < NN) {
                float2 v1 = make_float2(fmaxf(acc[mi][ni][2] + sb2[col], 0.f),
                                        fmaxf(acc[mi][ni][3] + sb2[col + 1], 0.f));
                *reinterpret_cast<float2*>(ob + (size_t)(row + 8) * HH + col) = v1;
            }
        }
}

extern "C" void kernel_launch(void* const* d_in, const int* in_sizes, int n_in,
                              void* d_out, int out_size)
{
    const float* a  = (const float*)d_in[0];
    const float* f  = (const float*)d_in[1];
    const float* W1 = (const float*)d_in[2];
    const float* b1 = (const float*)d_in[3];
    const float* W2 = (const float*)d_in[4];
    const float* b2 = (const float*)d_in[5];
    float* out = (float*)d_out;

    int batch = in_sizes[0] / (NN * NN);

    cudaFuncSetAttribute(gcn_mma, cudaFuncAttributeMaxDynamicSharedMemorySize, (int)SMEM_BYTES);
    gcn_mma<<<batch, NTHREADS, SMEM_BYTES>>>(a, f, W1, b1, W2, b2, out);
}